// round 7
// baseline (speedup 1.0000x reference)
#include <cuda_runtime.h>
#include <cstdint>

#define B_ 4
#define S_ 2048
#define D_ 1024
#define H_ 16
#define A_ 64

typedef unsigned long long u64t;

// Scratch: projected q/k/v heads, [3][B][H][S][A] fp32 (static => allocation-guard safe)
__device__ float g_ph[3][(size_t)B_ * H_ * S_ * A_];

// ---------------------------------------------------------------------------
// Packed fp32x2 helpers (plain sm_100 PTX ISA 8.6)
// ---------------------------------------------------------------------------
__device__ __forceinline__ u64t pk2(float lo, float hi) {
    u64t d;
    asm("mov.b64 %0, {%1, %2};" : "=l"(d) : "f"(lo), "f"(hi));
    return d;
}
__device__ __forceinline__ void upk2(float& lo, float& hi, u64t d) {
    asm("mov.b64 {%0, %1}, %2;" : "=f"(lo), "=f"(hi) : "l"(d));
}
__device__ __forceinline__ void fma2(u64t& d, u64t a, u64t b) {
    asm("fma.rn.f32x2 %0, %1, %2, %3;" : "=l"(d) : "l"(a), "l"(b), "l"(d));
}
__device__ __forceinline__ u64t mul2(u64t a, u64t b) {
    u64t d;
    asm("mul.rn.f32x2 %0, %1, %2;" : "=l"(d) : "l"(a), "l"(b));
    return d;
}

// ---------------------------------------------------------------------------
// Projection (unchanged from R5 passing kernel): 128x128 tile, 8x8/thread f32x2.
// Grid (64, 8, 3), block 256.
// ---------------------------------------------------------------------------
#define PKX 132

__global__ __launch_bounds__(256, 2) void proj_kernel(
    const float* __restrict__ q, const float* __restrict__ k, const float* __restrict__ v,
    const float* __restrict__ Wq, const float* __restrict__ bq,
    const float* __restrict__ Wk, const float* __restrict__ bk,
    const float* __restrict__ Wv, const float* __restrict__ bv)
{
    const int tid = threadIdx.x;
    const int ty = tid >> 4;
    const int tx = tid & 15;
    const int m0 = blockIdx.x * 128;
    const int h0 = blockIdx.y * 2;
    const int z = blockIdx.z;

    const float* x    = (z == 0) ? q  : (z == 1) ? k  : v;
    const float* W    = (z == 0) ? Wq : (z == 1) ? Wk : Wv;
    const float* bias = (z == 0) ? bq : (z == 1) ? bk : bv;

    __shared__ float Xs[16][PKX];
    __shared__ float Ws[16][PKX];

    const float* xbase = x + (size_t)m0 * D_;
    const float* wb = W + (size_t)h0 * D_ * A_;

    u64t acc2[8][4];
    #pragma unroll
    for (int i = 0; i < 8; i++)
        #pragma unroll
        for (int p = 0; p < 4; p++) acc2[i][p] = 0ull;

    for (int d0 = 0; d0 < D_; d0 += 16) {
        __syncthreads();
        #pragma unroll
        for (int j = 0; j < 2; j++) {
            int idx = tid + j * 256;
            int row = idx >> 2, c = (idx & 3) << 2;
            float4 xv = *(const float4*)(xbase + (size_t)row * D_ + d0 + c);
            Xs[c + 0][row] = xv.x;
            Xs[c + 1][row] = xv.y;
            Xs[c + 2][row] = xv.z;
            Xs[c + 3][row] = xv.w;
        }
        #pragma unroll
        for (int j = 0; j < 2; j++) {
            int idx = tid + j * 256;
            int d = idx >> 5, n4 = (idx & 31) << 2;
            int hh = n4 >> 6, a = n4 & 63;
            *(float4*)&Ws[d][n4] =
                *(const float4*)(wb + (size_t)hh * D_ * A_ + (size_t)(d0 + d) * A_ + a);
        }
        __syncthreads();

        #pragma unroll
        for (int kk = 0; kk < 16; kk++) {
            float4 q0 = *(float4*)&Xs[kk][ty * 8];
            float4 q1 = *(float4*)&Xs[kk][ty * 8 + 4];
            float4 w0 = *(float4*)&Ws[kk][tx * 4];
            float4 w1 = *(float4*)&Ws[kk][64 + tx * 4];
            u64t w2[4] = {pk2(w0.x, w0.y), pk2(w0.z, w0.w),
                          pk2(w1.x, w1.y), pk2(w1.z, w1.w)};
            float qa[8] = {q0.x, q0.y, q0.z, q0.w, q1.x, q1.y, q1.z, q1.w};
            #pragma unroll
            for (int i = 0; i < 8; i++) {
                u64t qq = pk2(qa[i], qa[i]);
                #pragma unroll
                for (int p = 0; p < 4; p++) fma2(acc2[i][p], qq, w2[p]);
            }
        }
    }

    float4 b0 = *(const float4*)(bias + h0 * A_ + tx * 4);
    float4 b1 = *(const float4*)(bias + (h0 + 1) * A_ + tx * 4);
    #pragma unroll
    for (int i = 0; i < 8; i++) {
        int row = m0 + ty * 8 + i;
        int b = row >> 11, s = row & (S_ - 1);
        float o0, o1, o2, o3;
        upk2(o0, o1, acc2[i][0]);
        upk2(o2, o3, acc2[i][1]);
        float4 r0 = make_float4(o0 + b0.x, o1 + b0.y, o2 + b0.z, o3 + b0.w);
        *(float4*)(g_ph[z] + ((((size_t)b * H_ + h0) * S_ + s) << 6) + tx * 4) = r0;
        upk2(o0, o1, acc2[i][2]);
        upk2(o2, o3, acc2[i][3]);
        float4 r1 = make_float4(o0 + b1.x, o1 + b1.y, o2 + b1.z, o3 + b1.w);
        *(float4*)(g_ph[z] + ((((size_t)b * H_ + h0 + 1) * S_ + s) << 6) + tx * 4) = r1;
    }
}

// ---------------------------------------------------------------------------
// Flash attention: 128-row Q tile x 64-col K tiles. smem = 103.4 KB -> 2 CTAs/SM.
// 256 threads, 8q x 4k per thread S-GEMM, 8q x 4a PV-GEMM, f32x2 FMA.
// Grid (S/128 = 16, B*H = 64), block 256.
// ---------------------------------------------------------------------------
#define PQK 132   // Qs padded row (floats)
#define PKS 68    // Ks/Vs/Ps padded row (floats)
#define QS_OFF 0
#define KS_OFF (64 * PQK)
#define VS_OFF (KS_OFF + 64 * PKS)
#define PS_OFF (VS_OFF + 64 * PKS)
#define ATTN_SMEM_FLOATS (PS_OFF + 128 * PKS)   // 25856 floats = 103,424 B

extern __shared__ float smem_attn[];

__global__ __launch_bounds__(256, 2) void attn_kernel(float* __restrict__ out)
{
    float* Qs = smem_attn + QS_OFF;   // [64 a][PQK] : Qs[a][row], row in [0,128)
    float* Ks = smem_attn + KS_OFF;   // [64 a][PKS] : Ks[a][col], col in [0,64)
    float* Vs = smem_attn + VS_OFF;   // [64 k][PKS] : Vs[k][a]
    float* Ps = smem_attn + PS_OFF;   // [128 q][PKS]: Ps[q][col]

    const int tid = threadIdx.x;
    const int ty = tid >> 4;          // 0..15 -> 8 q-rows
    const int tx = tid & 15;          // 0..15 -> 4 cols
    const int qtile = blockIdx.x;
    const int bh = blockIdx.y;
    const int b = bh / H_, h = bh % H_;

    const float* qh = g_ph[0] + (((size_t)b * H_ + h) * S_) * A_;
    const float* kh = g_ph[1] + (((size_t)b * H_ + h) * S_) * A_;
    const float* vh = g_ph[2] + (((size_t)b * H_ + h) * S_) * A_;

    // Load Q tile (128 rows x 64 a), transposed to a-major
    #pragma unroll
    for (int j = 0; j < 8; j++) {
        int idx = tid + j * 256;            // [0,2048)
        int row = idx >> 4, a4 = (idx & 15) << 2;
        float4 qv = *(const float4*)(qh + (size_t)(qtile * 128 + row) * A_ + a4);
        Qs[(a4 + 0) * PQK + row] = qv.x;
        Qs[(a4 + 1) * PQK + row] = qv.y;
        Qs[(a4 + 2) * PQK + row] = qv.z;
        Qs[(a4 + 3) * PQK + row] = qv.w;
    }

    float m[8], l[8];
    u64t o2[8][2];
    #pragma unroll
    for (int i = 0; i < 8; i++) {
        m[i] = -1e30f;
        l[i] = 0.0f;
        o2[i][0] = 0ull;
        o2[i][1] = 0ull;
    }

    for (int t = 0; t < S_ / 64; t++) {
        __syncthreads();   // previous iteration readers done with Ks/Vs/Ps
        // K tile (64 rows x 64 a, transposed) + V tile (direct): 1024 float4
        #pragma unroll
        for (int j = 0; j < 4; j++) {
            int idx = tid + j * 256;        // [0,1024)
            int krow = idx >> 4, a4 = (idx & 15) << 2;
            float4 kv = *(const float4*)(kh + (size_t)(t * 64 + krow) * A_ + a4);
            Ks[(a4 + 0) * PKS + krow] = kv.x;
            Ks[(a4 + 1) * PKS + krow] = kv.y;
            Ks[(a4 + 2) * PKS + krow] = kv.z;
            Ks[(a4 + 3) * PKS + krow] = kv.w;
            float4 vv = *(const float4*)(vh + (size_t)(t * 64 + krow) * A_ + a4);
            *(float4*)&Vs[krow * PKS + a4] = vv;
        }
        __syncthreads();

        // S = Q K^T : 8 rows x 4 cols per thread
        u64t s2[8][2];
        #pragma unroll
        for (int i = 0; i < 8; i++) { s2[i][0] = 0ull; s2[i][1] = 0ull; }

        #pragma unroll 8
        for (int a = 0; a < 64; a++) {
            float4 q0 = *(float4*)&Qs[a * PQK + ty * 8];
            float4 q1 = *(float4*)&Qs[a * PQK + ty * 8 + 4];
            float4 k0 = *(float4*)&Ks[a * PKS + tx * 4];
            u64t k2a = pk2(k0.x, k0.y);
            u64t k2b = pk2(k0.z, k0.w);
            float qa[8] = {q0.x, q0.y, q0.z, q0.w, q1.x, q1.y, q1.z, q1.w};
            #pragma unroll
            for (int i = 0; i < 8; i++) {
                u64t qq = pk2(qa[i], qa[i]);
                fma2(s2[i][0], qq, k2a);
                fma2(s2[i][1], qq, k2b);
            }
        }

        // Online softmax per q-row (row spread over 16 tx lanes; shfl width 16)
        #pragma unroll
        for (int i = 0; i < 8; i++) {
            float sv[4];
            upk2(sv[0], sv[1], s2[i][0]);
            upk2(sv[2], sv[3], s2[i][1]);
            float mt = fmaxf(fmaxf(sv[0], sv[1]), fmaxf(sv[2], sv[3]));
            #pragma unroll
            for (int off = 8; off; off >>= 1)
                mt = fmaxf(mt, __shfl_xor_sync(0xffffffffu, mt, off, 16));
            float mn = fmaxf(m[i], mt);
            float corr = __expf(m[i] - mn);
            m[i] = mn;
            float rs = 0.0f;
            #pragma unroll
            for (int j = 0; j < 4; j++) {
                sv[j] = __expf(sv[j] - mn);
                rs += sv[j];
            }
            #pragma unroll
            for (int off = 8; off; off >>= 1)
                rs += __shfl_xor_sync(0xffffffffu, rs, off, 16);
            l[i] = l[i] * corr + rs;
            u64t c2 = pk2(corr, corr);
            o2[i][0] = mul2(o2[i][0], c2);
            o2[i][1] = mul2(o2[i][1], c2);
            *(float4*)&Ps[(ty * 8 + i) * PKS + tx * 4] =
                make_float4(sv[0], sv[1], sv[2], sv[3]);
        }
        __syncthreads();

        // O += P V : 8 rows x 4 a-cols per thread; V-outer to bound registers
        #pragma unroll 2
        for (int k4 = 0; k4 < 16; k4++) {
            u64t v2[4][2];
            #pragma unroll
            for (int kk = 0; kk < 4; kk++) {
                float4 vv = *(float4*)&Vs[(k4 * 4 + kk) * PKS + tx * 4];
                v2[kk][0] = pk2(vv.x, vv.y);
                v2[kk][1] = pk2(vv.z, vv.w);
            }
            #pragma unroll
            for (int i = 0; i < 8; i++) {
                float4 p = *(float4*)&Ps[(ty * 8 + i) * PKS + k4 * 4];
                u64t pp;
                pp = pk2(p.x, p.x); fma2(o2[i][0], pp, v2[0][0]); fma2(o2[i][1], pp, v2[0][1]);
                pp = pk2(p.y, p.y); fma2(o2[i][0], pp, v2[1][0]); fma2(o2[i][1], pp, v2[1][1]);
                pp = pk2(p.z, p.z); fma2(o2[i][0], pp, v2[2][0]); fma2(o2[i][1], pp, v2[2][1]);
                pp = pk2(p.w, p.w); fma2(o2[i][0], pp, v2[3][0]); fma2(o2[i][1], pp, v2[3][1]);
            }
        }
    }

    // Normalize and store: out[b, s, h*A + a]
    #pragma unroll
    for (int i = 0; i < 8; i++) {
        float inv = 1.0f / l[i];
        int s = qtile * 128 + ty * 8 + i;
        float o0, o1, o2v, o3;
        upk2(o0, o1, o2[i][0]);
        upk2(o2v, o3, o2[i][1]);
        float4 r = make_float4(o0 * inv, o1 * inv, o2v * inv, o3 * inv);
        *(float4*)(out + ((size_t)b * S_ + s) * (H_ * A_) + h * A_ + tx * 4) = r;
    }
}

// ---------------------------------------------------------------------------
extern "C" void kernel_launch(void* const* d_in, const int* in_sizes, int n_in,
                              void* d_out, int out_size)
{
    const float* q  = (const float*)d_in[0];
    const float* k  = (const float*)d_in[1];
    const float* v  = (const float*)d_in[2];
    const float* Wq = (const float*)d_in[3];
    const float* bq = (const float*)d_in[4];
    const float* Wk = (const float*)d_in[5];
    const float* bk = (const float*)d_in[6];
    const float* Wv = (const float*)d_in[7];
    const float* bv = (const float*)d_in[8];

    const int attn_smem = ATTN_SMEM_FLOATS * (int)sizeof(float);   // 103,424 B
    cudaFuncSetAttribute(attn_kernel, cudaFuncAttributeMaxDynamicSharedMemorySize, attn_smem);

    dim3 pgrid(B_ * S_ / 128, H_ / 2, 3);
    proj_kernel<<<pgrid, 256>>>(q, k, v, Wq, bq, Wk, bk, Wv, bv);

    dim3 agrid(S_ / 128, B_ * H_);
    attn_kernel<<<agrid, 256, attn_smem>>>((float*)d_out);
}

// round 8
// speedup vs baseline: 1.3870x; 1.3870x over previous
#include <cuda_runtime.h>
#include <cuda_bf16.h>
#include <cstdint>

#define B_ 4
#define S_ 2048
#define D_ 1024
#define H_ 16
#define A_ 64

typedef unsigned long long u64t;

// Scratch: projected q/k/v heads, [3][B][H][S][A] fp32 (static => allocation-guard safe)
__device__ float g_ph[3][(size_t)B_ * H_ * S_ * A_];

// ---------------------------------------------------------------------------
// Packed fp32x2 helpers (plain sm_100)
// ---------------------------------------------------------------------------
__device__ __forceinline__ u64t pk2(float lo, float hi) {
    u64t d;
    asm("mov.b64 %0, {%1, %2};" : "=l"(d) : "f"(lo), "f"(hi));
    return d;
}
__device__ __forceinline__ void upk2(float& lo, float& hi, u64t d) {
    asm("mov.b64 {%0, %1}, %2;" : "=f"(lo), "=f"(hi) : "l"(d));
}
__device__ __forceinline__ void fma2(u64t& d, u64t a, u64t b) {
    asm("fma.rn.f32x2 %0, %1, %2, %3;" : "=l"(d) : "l"(a), "l"(b), "l"(d));
}

// bf16x2 pack: {lo -> bits[15:0], hi -> bits[31:16]}, round-to-nearest
__device__ __forceinline__ uint32_t pkbf(float lo, float hi) {
    uint32_t d;
    asm("cvt.rn.bf16x2.f32 %0, %1, %2;" : "=r"(d) : "f"(hi), "f"(lo));
    return d;
}
__device__ __forceinline__ float bfhi(float x) {      // float(bf16(x))
    return __bfloat162float(__float2bfloat16(x));
}

// mma.sync m16n8k16 row.col f32.bf16.bf16.f32 (sm_80+, legal on plain sm_100)
__device__ __forceinline__ void mma16816(float* d, const uint32_t* a, uint32_t b0, uint32_t b1) {
    asm("mma.sync.aligned.m16n8k16.row.col.f32.bf16.bf16.f32 "
        "{%0,%1,%2,%3}, {%4,%5,%6,%7}, {%8,%9}, {%0,%1,%2,%3};"
        : "+f"(d[0]), "+f"(d[1]), "+f"(d[2]), "+f"(d[3])
        : "r"(a[0]), "r"(a[1]), "r"(a[2]), "r"(a[3]), "r"(b0), "r"(b1));
}

// ---------------------------------------------------------------------------
// Projection (unchanged R5/R6 passing kernel): 128x128 tile, 8x8/thread f32x2.
// ---------------------------------------------------------------------------
#define PKX 132

__global__ __launch_bounds__(256, 2) void proj_kernel(
    const float* __restrict__ q, const float* __restrict__ k, const float* __restrict__ v,
    const float* __restrict__ Wq, const float* __restrict__ bq,
    const float* __restrict__ Wk, const float* __restrict__ bk,
    const float* __restrict__ Wv, const float* __restrict__ bv)
{
    const int tid = threadIdx.x;
    const int ty = tid >> 4;
    const int tx = tid & 15;
    const int m0 = blockIdx.x * 128;
    const int h0 = blockIdx.y * 2;
    const int z = blockIdx.z;

    const float* x    = (z == 0) ? q  : (z == 1) ? k  : v;
    const float* W    = (z == 0) ? Wq : (z == 1) ? Wk : Wv;
    const float* bias = (z == 0) ? bq : (z == 1) ? bk : bv;

    __shared__ float Xs[16][PKX];
    __shared__ float Ws[16][PKX];

    const float* xbase = x + (size_t)m0 * D_;
    const float* wb = W + (size_t)h0 * D_ * A_;

    u64t acc2[8][4];
    #pragma unroll
    for (int i = 0; i < 8; i++)
        #pragma unroll
        for (int p = 0; p < 4; p++) acc2[i][p] = 0ull;

    for (int d0 = 0; d0 < D_; d0 += 16) {
        __syncthreads();
        #pragma unroll
        for (int j = 0; j < 2; j++) {
            int idx = tid + j * 256;
            int row = idx >> 2, c = (idx & 3) << 2;
            float4 xv = *(const float4*)(xbase + (size_t)row * D_ + d0 + c);
            Xs[c + 0][row] = xv.x;
            Xs[c + 1][row] = xv.y;
            Xs[c + 2][row] = xv.z;
            Xs[c + 3][row] = xv.w;
        }
        #pragma unroll
        for (int j = 0; j < 2; j++) {
            int idx = tid + j * 256;
            int d = idx >> 5, n4 = (idx & 31) << 2;
            int hh = n4 >> 6, a = n4 & 63;
            *(float4*)&Ws[d][n4] =
                *(const float4*)(wb + (size_t)hh * D_ * A_ + (size_t)(d0 + d) * A_ + a);
        }
        __syncthreads();

        #pragma unroll
        for (int kk = 0; kk < 16; kk++) {
            float4 q0 = *(float4*)&Xs[kk][ty * 8];
            float4 q1 = *(float4*)&Xs[kk][ty * 8 + 4];
            float4 w0 = *(float4*)&Ws[kk][tx * 4];
            float4 w1 = *(float4*)&Ws[kk][64 + tx * 4];
            u64t w2[4] = {pk2(w0.x, w0.y), pk2(w0.z, w0.w),
                          pk2(w1.x, w1.y), pk2(w1.z, w1.w)};
            float qa[8] = {q0.x, q0.y, q0.z, q0.w, q1.x, q1.y, q1.z, q1.w};
            #pragma unroll
            for (int i = 0; i < 8; i++) {
                u64t qq = pk2(qa[i], qa[i]);
                #pragma unroll
                for (int p = 0; p < 4; p++) fma2(acc2[i][p], qq, w2[p]);
            }
        }
    }

    float4 b0 = *(const float4*)(bias + h0 * A_ + tx * 4);
    float4 b1 = *(const float4*)(bias + (h0 + 1) * A_ + tx * 4);
    #pragma unroll
    for (int i = 0; i < 8; i++) {
        int row = m0 + ty * 8 + i;
        int b = row >> 11, s = row & (S_ - 1);
        float o0, o1, o2, o3;
        upk2(o0, o1, acc2[i][0]);
        upk2(o2, o3, acc2[i][1]);
        float4 r0 = make_float4(o0 + b0.x, o1 + b0.y, o2 + b0.z, o3 + b0.w);
        *(float4*)(g_ph[z] + ((((size_t)b * H_ + h0) * S_ + s) << 6) + tx * 4) = r0;
        upk2(o0, o1, acc2[i][2]);
        upk2(o2, o3, acc2[i][3]);
        float4 r1 = make_float4(o0 + b1.x, o1 + b1.y, o2 + b1.z, o3 + b1.w);
        *(float4*)(g_ph[z] + ((((size_t)b * H_ + h0 + 1) * S_ + s) << 6) + tx * 4) = r1;
    }
}

// ---------------------------------------------------------------------------
// HMMA flash attention (mma.sync bf16, 2-way split on both operands):
//   CTA = 128 q-rows; 8 warps, warp w owns rows w*16..w*16+15.
//   K-tiles of 64 cols. P stays register-resident (S C-frag == PV A-frag).
// Grid (S/128 = 16, B*H = 64), block 256.
// ---------------------------------------------------------------------------
#define KST 36   // u32 stride of packed K/V smem rows (conflict-free B-frag reads)

__global__ __launch_bounds__(256) void attn_kernel(float* __restrict__ out)
{
    __shared__ uint32_t sKh[64 * KST];   // [kcol][aa] : packs K[kcol][2aa..2aa+1] hi
    __shared__ uint32_t sKl[64 * KST];
    __shared__ uint32_t sVh[64 * KST];   // [a][kk]    : packs V[2kk..2kk+1][a] hi
    __shared__ uint32_t sVl[64 * KST];

    const int tid = threadIdx.x;
    const int w = tid >> 5;
    const int lane = tid & 31;
    const int lq = lane >> 2;            // fragment row selector
    const int lc = lane & 3;             // fragment col selector
    const int qtile = blockIdx.x;
    const int bh = blockIdx.y;
    const int b = bh / H_, h = bh % H_;

    const float* qh_g = g_ph[0] + (((size_t)b * H_ + h) * S_) * A_;
    const float* kh_g = g_ph[1] + (((size_t)b * H_ + h) * S_) * A_;
    const float* vh_g = g_ph[2] + (((size_t)b * H_ + h) * S_) * A_;

    // --- Q fragments in registers (hi+lo split), rows w*16..+15 ---
    uint32_t qfh[4][4], qfl[4][4];
    {
        const int qr = qtile * 128 + w * 16;
        #pragma unroll
        for (int kt = 0; kt < 4; kt++) {
            #pragma unroll
            for (int j = 0; j < 4; j++) {
                int rr = lq + ((j & 1) ? 8 : 0);
                int cc = 16 * kt + 2 * lc + ((j >> 1) ? 8 : 0);
                float2 qv = *(const float2*)(qh_g + (size_t)(qr + rr) * A_ + cc);
                qfh[kt][j] = pkbf(qv.x, qv.y);
                qfl[kt][j] = pkbf(qv.x - bfhi(qv.x), qv.y - bfhi(qv.y));
            }
        }
    }

    float m0 = -1e30f, m1 = -1e30f, l0 = 0.0f, l1 = 0.0f;
    float O[8][4];
    #pragma unroll
    for (int nt = 0; nt < 8; nt++)
        #pragma unroll
        for (int j = 0; j < 4; j++) O[nt][j] = 0.0f;

    for (int t = 0; t < S_ / 64; t++) {
        __syncthreads();   // previous iteration done reading smem

        // --- K tile loader: 64 kcol x 64 a -> packed [kcol][aa] hi/lo ---
        #pragma unroll
        for (int j = 0; j < 4; j++) {
            int idx = tid + j * 256;                 // [0,1024)
            int kcol = idx >> 4, g = idx & 15;
            float4 kv = *(const float4*)(kh_g + (size_t)(t * 64 + kcol) * A_ + 4 * g);
            uint32_t h0p = pkbf(kv.x, kv.y);
            uint32_t h1p = pkbf(kv.z, kv.w);
            uint32_t l0p = pkbf(kv.x - bfhi(kv.x), kv.y - bfhi(kv.y));
            uint32_t l1p = pkbf(kv.z - bfhi(kv.z), kv.w - bfhi(kv.w));
            int base = kcol * KST + 2 * g;
            sKh[base] = h0p; sKh[base + 1] = h1p;
            sKl[base] = l0p; sKl[base + 1] = l1p;
        }
        // --- V tile loader: pack pairs along k: [a][kk] hi/lo ---
        #pragma unroll
        for (int j = 0; j < 2; j++) {
            int kk = lane;                            // 0..31 (k-pair)
            int g = w + 8 * j;                        // 0..15 (a-group of 4)
            const float* src = vh_g + (size_t)(t * 64 + 2 * kk) * A_ + 4 * g;
            float4 v0 = *(const float4*)(src);
            float4 v1 = *(const float4*)(src + A_);
            float e0[4] = {v0.x, v0.y, v0.z, v0.w};
            float e1[4] = {v1.x, v1.y, v1.z, v1.w};
            #pragma unroll
            for (int i = 0; i < 4; i++) {
                int a = 4 * g + i;
                sVh[a * KST + kk] = pkbf(e0[i], e1[i]);
                sVl[a * KST + kk] = pkbf(e0[i] - bfhi(e0[i]), e1[i] - bfhi(e1[i]));
            }
        }
        __syncthreads();

        // --- S = Q K^T (3-term bf16 split), warp tile 16x64 ---
        float c[8][4];
        #pragma unroll
        for (int nt = 0; nt < 8; nt++)
            #pragma unroll
            for (int j = 0; j < 4; j++) c[nt][j] = 0.0f;

        #pragma unroll
        for (int kt = 0; kt < 4; kt++) {
            #pragma unroll
            for (int nt = 0; nt < 8; nt++) {
                int ba = (8 * nt + lq) * KST + 8 * kt + lc;
                uint32_t kh0 = sKh[ba], kh1 = sKh[ba + 4];
                uint32_t kl0 = sKl[ba], kl1 = sKl[ba + 4];
                mma16816(c[nt], qfh[kt], kh0, kh1);
                mma16816(c[nt], qfh[kt], kl0, kl1);
                mma16816(c[nt], qfl[kt], kh0, kh1);
            }
        }

        // --- online softmax (rows lq and lq+8; quad = 4 consecutive lanes) ---
        float mx0 = -1e30f, mx1 = -1e30f;
        #pragma unroll
        for (int nt = 0; nt < 8; nt++) {
            mx0 = fmaxf(mx0, fmaxf(c[nt][0], c[nt][1]));
            mx1 = fmaxf(mx1, fmaxf(c[nt][2], c[nt][3]));
        }
        mx0 = fmaxf(mx0, __shfl_xor_sync(0xffffffffu, mx0, 1, 4));
        mx0 = fmaxf(mx0, __shfl_xor_sync(0xffffffffu, mx0, 2, 4));
        mx1 = fmaxf(mx1, __shfl_xor_sync(0xffffffffu, mx1, 1, 4));
        mx1 = fmaxf(mx1, __shfl_xor_sync(0xffffffffu, mx1, 2, 4));
        float mn0 = fmaxf(m0, mx0), mn1 = fmaxf(m1, mx1);
        float corr0 = __expf(m0 - mn0), corr1 = __expf(m1 - mn1);
        m0 = mn0; m1 = mn1;

        float rs0 = 0.0f, rs1 = 0.0f;
        #pragma unroll
        for (int nt = 0; nt < 8; nt++) {
            c[nt][0] = __expf(c[nt][0] - mn0);
            c[nt][1] = __expf(c[nt][1] - mn0);
            c[nt][2] = __expf(c[nt][2] - mn1);
            c[nt][3] = __expf(c[nt][3] - mn1);
            rs0 += c[nt][0] + c[nt][1];
            rs1 += c[nt][2] + c[nt][3];
        }
        rs0 += __shfl_xor_sync(0xffffffffu, rs0, 1, 4);
        rs0 += __shfl_xor_sync(0xffffffffu, rs0, 2, 4);
        rs1 += __shfl_xor_sync(0xffffffffu, rs1, 1, 4);
        rs1 += __shfl_xor_sync(0xffffffffu, rs1, 2, 4);
        l0 = l0 * corr0 + rs0;
        l1 = l1 * corr1 + rs1;

        #pragma unroll
        for (int nt = 0; nt < 8; nt++) {
            O[nt][0] *= corr0; O[nt][1] *= corr0;
            O[nt][2] *= corr1; O[nt][3] *= corr1;
        }

        // --- P fragments (register-resident; C-frag(2kt,2kt+1) == A-frag(kt)) ---
        uint32_t pfh[4][4], pfl[4][4];
        #pragma unroll
        for (int kt = 0; kt < 4; kt++) {
            float* ca = c[2 * kt];
            float* cb = c[2 * kt + 1];
            pfh[kt][0] = pkbf(ca[0], ca[1]);
            pfh[kt][1] = pkbf(ca[2], ca[3]);
            pfh[kt][2] = pkbf(cb[0], cb[1]);
            pfh[kt][3] = pkbf(cb[2], cb[3]);
            pfl[kt][0] = pkbf(ca[0] - bfhi(ca[0]), ca[1] - bfhi(ca[1]));
            pfl[kt][1] = pkbf(ca[2] - bfhi(ca[2]), ca[3] - bfhi(ca[3]));
            pfl[kt][2] = pkbf(cb[0] - bfhi(cb[0]), cb[1] - bfhi(cb[1]));
            pfl[kt][3] = pkbf(cb[2] - bfhi(cb[2]), cb[3] - bfhi(cb[3]));
        }

        // --- O += P V (3-term split) ---
        #pragma unroll
        for (int kt = 0; kt < 4; kt++) {
            #pragma unroll
            for (int nt = 0; nt < 8; nt++) {
                int ba = (8 * nt + lq) * KST + 8 * kt + lc;
                uint32_t vh0 = sVh[ba], vh1 = sVh[ba + 4];
                uint32_t vl0 = sVl[ba], vl1 = sVl[ba + 4];
                mma16816(O[nt], pfh[kt], vh0, vh1);
                mma16816(O[nt], pfh[kt], vl0, vl1);
                mma16816(O[nt], pfl[kt], vh0, vh1);
            }
        }
    }

    // --- epilogue: normalize, store out[b, s, h*64 + a] ---
    const float inv0 = 1.0f / l0, inv1 = 1.0f / l1;
    const int s0 = qtile * 128 + w * 16 + lq;
    const int s1 = s0 + 8;
    float* ob0 = out + ((size_t)b * S_ + s0) * (H_ * A_) + h * A_ + 2 * lc;
    float* ob1 = out + ((size_t)b * S_ + s1) * (H_ * A_) + h * A_ + 2 * lc;
    #pragma unroll
    for (int nt = 0; nt < 8; nt++) {
        *(float2*)(ob0 + 8 * nt) = make_float2(O[nt][0] * inv0, O[nt][1] * inv0);
        *(float2*)(ob1 + 8 * nt) = make_float2(O[nt][2] * inv1, O[nt][3] * inv1);
    }
}

// ---------------------------------------------------------------------------
extern "C" void kernel_launch(void* const* d_in, const int* in_sizes, int n_in,
                              void* d_out, int out_size)
{
    const float* q  = (const float*)d_in[0];
    const float* k  = (const float*)d_in[1];
    const float* v  = (const float*)d_in[2];
    const float* Wq = (const float*)d_in[3];
    const float* bq = (const float*)d_in[4];
    const float* Wk = (const float*)d_in[5];
    const float* bk = (const float*)d_in[6];
    const float* Wv = (const float*)d_in[7];
    const float* bv = (const float*)d_in[8];

    dim3 pgrid(B_ * S_ / 128, H_ / 2, 3);
    proj_kernel<<<pgrid, 256>>>(q, k, v, Wq, bq, Wk, bk, Wv, bv);

    dim3 agrid(S_ / 128, B_ * H_);
    attn_kernel<<<agrid, 256>>>((float*)d_out);
}

// round 9
// speedup vs baseline: 1.8761x; 1.3526x over previous
#include <cuda_runtime.h>
#include <cuda_bf16.h>
#include <cstdint>

#define B_ 4
#define S_ 2048
#define D_ 1024
#define H_ 16
#define A_ 64
#define DP_ 512   // d-pairs per row (D/2)

// ---------------------------------------------------------------------------
// Device scratch (static => allocation-guard safe)
// ---------------------------------------------------------------------------
__device__ float g_ph[3][(size_t)B_ * H_ * S_ * A_];             // projected heads
__device__ uint32_t g_xph[3][(size_t)B_ * S_ * DP_];             // X packed bf16x2 hi
__device__ uint32_t g_xpl[3][(size_t)B_ * S_ * DP_];             // X packed bf16x2 lo
__device__ uint32_t g_wph[3][(size_t)H_ * A_ * DP_];             // Wt packed hi [n=(h,a)][dp]
__device__ uint32_t g_wpl[3][(size_t)H_ * A_ * DP_];             // Wt packed lo

// ---------------------------------------------------------------------------
// Helpers
// ---------------------------------------------------------------------------
__device__ __forceinline__ uint32_t pkbf(float lo, float hi) {   // {lo,hi} -> bf16x2
    uint32_t d;
    asm("cvt.rn.bf16x2.f32 %0, %1, %2;" : "=r"(d) : "f"(hi), "f"(lo));
    return d;
}
__device__ __forceinline__ float bfhi(float x) {                 // float(bf16(x))
    return __bfloat162float(__float2bfloat16(x));
}
// mma.sync m16n8k16 row.col f32.bf16.bf16.f32 (sm_80+, legal on plain sm_100)
__device__ __forceinline__ void mma16816(float* d, const uint32_t* a, uint32_t b0, uint32_t b1) {
    asm("mma.sync.aligned.m16n8k16.row.col.f32.bf16.bf16.f32 "
        "{%0,%1,%2,%3}, {%4,%5,%6,%7}, {%8,%9}, {%0,%1,%2,%3};"
        : "+f"(d[0]), "+f"(d[1]), "+f"(d[2]), "+f"(d[3])
        : "r"(a[0]), "r"(a[1]), "r"(a[2]), "r"(a[3]), "r"(b0), "r"(b1));
}

// ---------------------------------------------------------------------------
// Prepass 1: X -> packed bf16x2 hi/lo. Grid (4096, 3), block 256.
// Each thread: 4 d-pairs (8 floats).
// ---------------------------------------------------------------------------
__global__ __launch_bounds__(256) void x_prep(const float* __restrict__ q,
                                              const float* __restrict__ k,
                                              const float* __restrict__ v) {
    const int z = blockIdx.y;
    const float* x = (z == 0) ? q : (z == 1) ? k : v;
    size_t t = (size_t)blockIdx.x * 256 + threadIdx.x;
    float4 a = *(const float4*)(x + 8 * t);
    float4 b = *(const float4*)(x + 8 * t + 4);
    float e[8] = {a.x, a.y, a.z, a.w, b.x, b.y, b.z, b.w};
    uint4 hv, lv;
    uint32_t* hp = (uint32_t*)&hv;
    uint32_t* lp = (uint32_t*)&lv;
    #pragma unroll
    for (int i = 0; i < 4; i++) {
        float e0 = e[2 * i], e1 = e[2 * i + 1];
        hp[i] = pkbf(e0, e1);
        lp[i] = pkbf(e0 - bfhi(e0), e1 - bfhi(e1));
    }
    *(uint4*)&g_xph[z][4 * t] = hv;
    *(uint4*)&g_xpl[z][4 * t] = lv;
}

// ---------------------------------------------------------------------------
// Prepass 2: W[h][d][a] -> Wt packed [n=(h,a)][dp] hi/lo. Grid (16,16,3), block 256.
// ---------------------------------------------------------------------------
__global__ __launch_bounds__(256) void wt_prep(const float* __restrict__ Wq,
                                               const float* __restrict__ Wk,
                                               const float* __restrict__ Wv) {
    const int z = blockIdx.z, h = blockIdx.y, dt = blockIdx.x;
    const float* W = (z == 0) ? Wq : (z == 1) ? Wk : Wv;
    __shared__ float ts[64][65];
    const float* src = W + ((size_t)h * D_ + dt * 64) * A_;
    const int tid = threadIdx.x;
    #pragma unroll
    for (int j = 0; j < 16; j++) {
        int idx = tid + j * 256;            // [0,4096)
        int dr = idx >> 6, a = idx & 63;
        ts[dr][a] = src[(size_t)dr * A_ + a];
    }
    __syncthreads();
    #pragma unroll
    for (int j = 0; j < 8; j++) {
        int idx = tid + j * 256;            // [0,2048)
        int a = idx >> 5, dp = idx & 31;
        float f0 = ts[2 * dp][a];
        float f1 = ts[2 * dp + 1][a];
        size_t off = ((size_t)(h * 64 + a)) * DP_ + dt * 32 + dp;
        g_wph[z][off] = pkbf(f0, f1);
        g_wpl[z][off] = pkbf(f0 - bfhi(f0), f1 - bfhi(f1));
    }
}

// ---------------------------------------------------------------------------
// HMMA projection: out[r, n] = X[r,:] @ Wt[n,:] + bias  (3-term bf16 split)
// CTA: 128 rows x 128 cols (2 heads); 8 warps x (16m x 128n); K-chunks of 64.
// smem 73,728 B dynamic -> 2 CTAs/SM. Grid (64, 8, 3), block 256.
// ---------------------------------------------------------------------------
#define PST 36    // u32 stride of packed smem rows (conflict-free frag reads)

extern __shared__ uint32_t psm[];

__global__ __launch_bounds__(256, 2) void proj_mma(
    const float* __restrict__ bq, const float* __restrict__ bk, const float* __restrict__ bv)
{
    uint32_t* sXh = psm;                  // [128 rows][PST]
    uint32_t* sXl = psm + 128 * PST;      // +4608
    uint32_t* sWh = psm + 2 * 128 * PST;  // [128 n][PST]
    uint32_t* sWl = psm + 3 * 128 * PST;  // total 18432 u32 = 73728 B

    const int tid = threadIdx.x;
    const int w = tid >> 5;
    const int lane = tid & 31;
    const int lq = lane >> 2;
    const int lc = lane & 3;
    const int m0 = blockIdx.x * 128;
    const int h0 = blockIdx.y * 2;
    const int z = blockIdx.z;

    const float* bias = (z == 0) ? bq : (z == 1) ? bk : bv;
    const uint32_t* xh = g_xph[z];
    const uint32_t* xl = g_xpl[z];
    const uint32_t* wh = g_wph[z] + (size_t)h0 * A_ * DP_;
    const uint32_t* wl = g_wpl[z] + (size_t)h0 * A_ * DP_;

    float acc[16][4];
    #pragma unroll
    for (int nt = 0; nt < 16; nt++)
        #pragma unroll
        for (int j = 0; j < 4; j++) acc[nt][j] = 0.0f;

    for (int c = 0; c < 16; c++) {        // 16 K-chunks of 64 (32 d-pairs)
        const int d0p = c * 32;
        __syncthreads();
        // X loader: 128 rows x 8 uint4-groups
        #pragma unroll
        for (int j = 0; j < 4; j++) {
            int idx = tid + j * 256;          // [0,1024)
            int row = idx >> 3, g4 = (idx & 7) * 4;
            size_t src = (size_t)(m0 + row) * DP_ + d0p + g4;
            *(uint4*)&sXh[row * PST + g4] = *(const uint4*)&xh[src];
            *(uint4*)&sXl[row * PST + g4] = *(const uint4*)&xl[src];
        }
        // W loader: 128 n x 8 uint4-groups
        #pragma unroll
        for (int j = 0; j < 4; j++) {
            int idx = tid + j * 256;          // [0,1024)
            int n = idx >> 3, g4 = (idx & 7) * 4;
            size_t src = (size_t)n * DP_ + d0p + g4;
            *(uint4*)&sWh[n * PST + g4] = *(const uint4*)&wh[src];
            *(uint4*)&sWl[n * PST + g4] = *(const uint4*)&wl[src];
        }
        __syncthreads();

        #pragma unroll
        for (int kt = 0; kt < 4; kt++) {
            uint32_t ah[4], al[4];
            int r0 = (w * 16 + lq) * PST + 8 * kt + lc;
            int r1 = r0 + 8 * PST;
            ah[0] = sXh[r0]; ah[1] = sXh[r1]; ah[2] = sXh[r0 + 4]; ah[3] = sXh[r1 + 4];
            al[0] = sXl[r0]; al[1] = sXl[r1]; al[2] = sXl[r0 + 4]; al[3] = sXl[r1 + 4];
            #pragma unroll
            for (int nt = 0; nt < 16; nt++) {
                int ba = (8 * nt + lq) * PST + 8 * kt + lc;
                uint32_t wh0 = sWh[ba], wh1 = sWh[ba + 4];
                uint32_t wl0 = sWl[ba], wl1 = sWl[ba + 4];
                mma16816(acc[nt], ah, wh0, wh1);
                mma16816(acc[nt], ah, wl0, wl1);
                mma16816(acc[nt], al, wh0, wh1);
            }
        }
    }

    // Epilogue: bias + store to g_ph[z][b][h][s][a]
    const int row0 = m0 + w * 16 + lq;
    const int row1 = row0 + 8;
    const int b = row0 >> 11;
    const int s0 = row0 & (S_ - 1), s1 = row1 & (S_ - 1);
    #pragma unroll
    for (int nt = 0; nt < 16; nt++) {
        int col = 8 * nt + 2 * lc;
        int hl = col >> 6, a = col & 63;
        float2 bb = *(const float2*)(bias + (h0 + hl) * A_ + a);
        float* d0 = g_ph[z] + ((((size_t)b * H_ + h0 + hl) * S_ + s0) << 6) + a;
        float* d1 = g_ph[z] + ((((size_t)b * H_ + h0 + hl) * S_ + s1) << 6) + a;
        *(float2*)d0 = make_float2(acc[nt][0] + bb.x, acc[nt][1] + bb.y);
        *(float2*)d1 = make_float2(acc[nt][2] + bb.x, acc[nt][3] + bb.y);
    }
}

// ---------------------------------------------------------------------------
// HMMA flash attention (unchanged from R7 passing kernel)
// ---------------------------------------------------------------------------
#define KST 36

__global__ __launch_bounds__(256) void attn_kernel(float* __restrict__ out)
{
    __shared__ uint32_t sKh[64 * KST];
    __shared__ uint32_t sKl[64 * KST];
    __shared__ uint32_t sVh[64 * KST];
    __shared__ uint32_t sVl[64 * KST];

    const int tid = threadIdx.x;
    const int w = tid >> 5;
    const int lane = tid & 31;
    const int lq = lane >> 2;
    const int lc = lane & 3;
    const int qtile = blockIdx.x;
    const int bh = blockIdx.y;
    const int b = bh / H_, h = bh % H_;

    const float* qh_g = g_ph[0] + (((size_t)b * H_ + h) * S_) * A_;
    const float* kh_g = g_ph[1] + (((size_t)b * H_ + h) * S_) * A_;
    const float* vh_g = g_ph[2] + (((size_t)b * H_ + h) * S_) * A_;

    uint32_t qfh[4][4], qfl[4][4];
    {
        const int qr = qtile * 128 + w * 16;
        #pragma unroll
        for (int kt = 0; kt < 4; kt++) {
            #pragma unroll
            for (int j = 0; j < 4; j++) {
                int rr = lq + ((j & 1) ? 8 : 0);
                int cc = 16 * kt + 2 * lc + ((j >> 1) ? 8 : 0);
                float2 qv = *(const float2*)(qh_g + (size_t)(qr + rr) * A_ + cc);
                qfh[kt][j] = pkbf(qv.x, qv.y);
                qfl[kt][j] = pkbf(qv.x - bfhi(qv.x), qv.y - bfhi(qv.y));
            }
        }
    }

    float m0 = -1e30f, m1 = -1e30f, l0 = 0.0f, l1 = 0.0f;
    float O[8][4];
    #pragma unroll
    for (int nt = 0; nt < 8; nt++)
        #pragma unroll
        for (int j = 0; j < 4; j++) O[nt][j] = 0.0f;

    for (int t = 0; t < S_ / 64; t++) {
        __syncthreads();

        #pragma unroll
        for (int j = 0; j < 4; j++) {
            int idx = tid + j * 256;
            int kcol = idx >> 4, g = idx & 15;
            float4 kv = *(const float4*)(kh_g + (size_t)(t * 64 + kcol) * A_ + 4 * g);
            uint32_t h0p = pkbf(kv.x, kv.y);
            uint32_t h1p = pkbf(kv.z, kv.w);
            uint32_t l0p = pkbf(kv.x - bfhi(kv.x), kv.y - bfhi(kv.y));
            uint32_t l1p = pkbf(kv.z - bfhi(kv.z), kv.w - bfhi(kv.w));
            int base = kcol * KST + 2 * g;
            sKh[base] = h0p; sKh[base + 1] = h1p;
            sKl[base] = l0p; sKl[base + 1] = l1p;
        }
        #pragma unroll
        for (int j = 0; j < 2; j++) {
            int kk = lane;
            int g = w + 8 * j;
            const float* src = vh_g + (size_t)(t * 64 + 2 * kk) * A_ + 4 * g;
            float4 v0 = *(const float4*)(src);
            float4 v1 = *(const float4*)(src + A_);
            float e0[4] = {v0.x, v0.y, v0.z, v0.w};
            float e1[4] = {v1.x, v1.y, v1.z, v1.w};
            #pragma unroll
            for (int i = 0; i < 4; i++) {
                int a = 4 * g + i;
                sVh[a * KST + kk] = pkbf(e0[i], e1[i]);
                sVl[a * KST + kk] = pkbf(e0[i] - bfhi(e0[i]), e1[i] - bfhi(e1[i]));
            }
        }
        __syncthreads();

        float c[8][4];
        #pragma unroll
        for (int nt = 0; nt < 8; nt++)
            #pragma unroll
            for (int j = 0; j < 4; j++) c[nt][j] = 0.0f;

        #pragma unroll
        for (int kt = 0; kt < 4; kt++) {
            #pragma unroll
            for (int nt = 0; nt < 8; nt++) {
                int ba = (8 * nt + lq) * KST + 8 * kt + lc;
                uint32_t kh0 = sKh[ba], kh1 = sKh[ba + 4];
                uint32_t kl0 = sKl[ba], kl1 = sKl[ba + 4];
                mma16816(c[nt], qfh[kt], kh0, kh1);
                mma16816(c[nt], qfh[kt], kl0, kl1);
                mma16816(c[nt], qfl[kt], kh0, kh1);
            }
        }

        float mx0 = -1e30f, mx1 = -1e30f;
        #pragma unroll
        for (int nt = 0; nt < 8; nt++) {
            mx0 = fmaxf(mx0, fmaxf(c[nt][0], c[nt][1]));
            mx1 = fmaxf(mx1, fmaxf(c[nt][2], c[nt][3]));
        }
        mx0 = fmaxf(mx0, __shfl_xor_sync(0xffffffffu, mx0, 1, 4));
        mx0 = fmaxf(mx0, __shfl_xor_sync(0xffffffffu, mx0, 2, 4));
        mx1 = fmaxf(mx1, __shfl_xor_sync(0xffffffffu, mx1, 1, 4));
        mx1 = fmaxf(mx1, __shfl_xor_sync(0xffffffffu, mx1, 2, 4));
        float mn0 = fmaxf(m0, mx0), mn1 = fmaxf(m1, mx1);
        float corr0 = __expf(m0 - mn0), corr1 = __expf(m1 - mn1);
        m0 = mn0; m1 = mn1;

        float rs0 = 0.0f, rs1 = 0.0f;
        #pragma unroll
        for (int nt = 0; nt < 8; nt++) {
            c[nt][0] = __expf(c[nt][0] - mn0);
            c[nt][1] = __expf(c[nt][1] - mn0);
            c[nt][2] = __expf(c[nt][2] - mn1);
            c[nt][3] = __expf(c[nt][3] - mn1);
            rs0 += c[nt][0] + c[nt][1];
            rs1 += c[nt][2] + c[nt][3];
        }
        rs0 += __shfl_xor_sync(0xffffffffu, rs0, 1, 4);
        rs0 += __shfl_xor_sync(0xffffffffu, rs0, 2, 4);
        rs1 += __shfl_xor_sync(0xffffffffu, rs1, 1, 4);
        rs1 += __shfl_xor_sync(0xffffffffu, rs1, 2, 4);
        l0 = l0 * corr0 + rs0;
        l1 = l1 * corr1 + rs1;

        #pragma unroll
        for (int nt = 0; nt < 8; nt++) {
            O[nt][0] *= corr0; O[nt][1] *= corr0;
            O[nt][2] *= corr1; O[nt][3] *= corr1;
        }

        uint32_t pfh[4][4], pfl[4][4];
        #pragma unroll
        for (int kt = 0; kt < 4; kt++) {
            float* ca = c[2 * kt];
            float* cb = c[2 * kt + 1];
            pfh[kt][0] = pkbf(ca[0], ca[1]);
            pfh[kt][1] = pkbf(ca[2], ca[3]);
            pfh[kt][2] = pkbf(cb[0], cb[1]);
            pfh[kt][3] = pkbf(cb[2], cb[3]);
            pfl[kt][0] = pkbf(ca[0] - bfhi(ca[0]), ca[1] - bfhi(ca[1]));
            pfl[kt][1] = pkbf(ca[2] - bfhi(ca[2]), ca[3] - bfhi(ca[3]));
            pfl[kt][2] = pkbf(cb[0] - bfhi(cb[0]), cb[1] - bfhi(cb[1]));
            pfl[kt][3] = pkbf(cb[2] - bfhi(cb[2]), cb[3] - bfhi(cb[3]));
        }

        #pragma unroll
        for (int kt = 0; kt < 4; kt++) {
            #pragma unroll
            for (int nt = 0; nt < 8; nt++) {
                int ba = (8 * nt + lq) * KST + 8 * kt + lc;
                uint32_t vh0 = sVh[ba], vh1 = sVh[ba + 4];
                uint32_t vl0 = sVl[ba], vl1 = sVl[ba + 4];
                mma16816(O[nt], pfh[kt], vh0, vh1);
                mma16816(O[nt], pfh[kt], vl0, vl1);
                mma16816(O[nt], pfl[kt], vh0, vh1);
            }
        }
    }

    const float inv0 = 1.0f / l0, inv1 = 1.0f / l1;
    const int s0 = qtile * 128 + w * 16 + lq;
    const int s1 = s0 + 8;
    float* ob0 = out + ((size_t)b * S_ + s0) * (H_ * A_) + h * A_ + 2 * lc;
    float* ob1 = out + ((size_t)b * S_ + s1) * (H_ * A_) + h * A_ + 2 * lc;
    #pragma unroll
    for (int nt = 0; nt < 8; nt++) {
        *(float2*)(ob0 + 8 * nt) = make_float2(O[nt][0] * inv0, O[nt][1] * inv0);
        *(float2*)(ob1 + 8 * nt) = make_float2(O[nt][2] * inv1, O[nt][3] * inv1);
    }
}

// ---------------------------------------------------------------------------
extern "C" void kernel_launch(void* const* d_in, const int* in_sizes, int n_in,
                              void* d_out, int out_size)
{
    const float* q  = (const float*)d_in[0];
    const float* k  = (const float*)d_in[1];
    const float* v  = (const float*)d_in[2];
    const float* Wq = (const float*)d_in[3];
    const float* bq = (const float*)d_in[4];
    const float* Wk = (const float*)d_in[5];
    const float* bk = (const float*)d_in[6];
    const float* Wv = (const float*)d_in[7];
    const float* bv = (const float*)d_in[8];

    const int proj_smem = 4 * 128 * PST * (int)sizeof(uint32_t);   // 73,728 B
    cudaFuncSetAttribute(proj_mma, cudaFuncAttributeMaxDynamicSharedMemorySize, proj_smem);

    // 1) pack X and W into bf16x2 hi/lo
    x_prep<<<dim3((B_ * S_ * DP_) / (256 * 4), 3), 256>>>(q, k, v);
    wt_prep<<<dim3(16, 16, 3), 256>>>(Wq, Wk, Wv);

    // 2) HMMA projection
    proj_mma<<<dim3(B_ * S_ / 128, H_ / 2, 3), 256, proj_smem>>>(bq, bk, bv);

    // 3) HMMA flash attention
    attn_kernel<<<dim3(S_ / 128, B_ * H_), 256>>>((float*)d_out);
}